// round 11
// baseline (speedup 1.0000x reference)
#include <cuda_runtime.h>
#include <cuda_bf16.h>
#include <cstdint>
#include <cstddef>

// CombineGraph: h = emb[inputs]; e_k = leakyrelu(einsum(bid,bjd,d->bij; h,h,a_k));
// alpha = softmax(select_by_adj(e_k, -9e15)); out = alpha @ h.
// B=512, L=100, D=128. One CTA/batch, 2 CTA/SM.
// GEMM1 symmetry: 28 upper-triangle m32xn8 tiles; scaled-B shared across two m16
// A-tiles -> 1 mul.bf16x2 per mma. Mirror writes with coverage-skip (no races).
// GEMM2: tf32 mma.sync, swizzled resident h f32. Softmax via float4 rows.

#define B_    512
#define L_    100
#define D_    128
#define HB    68         // hb row stride (u32 words): 272B/row -> ldmatrix conflict-free
#define AS    108        // alpha row stride (floats)
#define ADJS  112        // adj row stride (bytes)
#define NEG_INF_ -9e15f

// ---- smem byte offsets ----
#define OFF_H    0            // h f32 swizzled: 104*128*4 = 53248 (resident throughout)
#define OFF_HB   53248        // hb bf16: 104*68*4 = 28288
#define OFF_ATP  81536        // a packed uint4[64] = 1024
#define OFF_ADJ  82560        // adj int8: 100*112 = 11200 (end 93760)
#define OFF_AL   53248        // alpha overlays hb/atp/adj: 104*108*4 = 44928 (end 98176)
#define SMEM_TOTAL 98176

// h f32 swizzle: conflict-free for STS.128 write and GEMM2 B-fragment read
#define HW(r, c) ((r) * 128 + ((c) ^ (((r) & 3) << 3)))

__device__ __forceinline__ uint32_t smem_u32(const void* p) {
    uint32_t a;
    asm("{ .reg .u64 t; cvta.to.shared.u64 t, %1; cvt.u32.u64 %0, t; }" : "=r"(a) : "l"(p));
    return a;
}
__device__ __forceinline__ float rna_tf32(float x) {
    unsigned u; asm("cvt.rna.tf32.f32 %0, %1;" : "=r"(u) : "f"(x));
    return __uint_as_float(u);
}
__device__ __forceinline__ unsigned pack_bf16x2(float lo, float hi) {
    unsigned r; asm("cvt.rn.satfinite.bf16x2.f32 %0, %1, %2;" : "=r"(r) : "f"(hi), "f"(lo));
    return r;
}
__device__ __forceinline__ unsigned mulbf2(unsigned a, unsigned b) {
    unsigned r; asm("mul.bf16x2 %0, %1, %2;" : "=r"(r) : "r"(a), "r"(b));
    return r;
}
__device__ __forceinline__ void ldsm_x4(unsigned& r0, unsigned& r1, unsigned& r2, unsigned& r3,
                                        uint32_t addr) {
    asm volatile("ldmatrix.sync.aligned.m8n8.x4.shared.b16 {%0,%1,%2,%3}, [%4];"
                 : "=r"(r0), "=r"(r1), "=r"(r2), "=r"(r3) : "r"(addr));
}
__device__ __forceinline__ void ldsm_x2(unsigned& r0, unsigned& r1, uint32_t addr) {
    asm volatile("ldmatrix.sync.aligned.m8n8.x2.shared.b16 {%0,%1}, [%2];"
                 : "=r"(r0), "=r"(r1) : "r"(addr));
}
__device__ __forceinline__ void mma_bf16(float* c, unsigned a0, unsigned a1,
                                         unsigned a2, unsigned a3,
                                         unsigned b0, unsigned b1) {
    asm volatile(
        "mma.sync.aligned.m16n8k16.row.col.f32.bf16.bf16.f32 "
        "{%0,%1,%2,%3},{%4,%5,%6,%7},{%8,%9},{%0,%1,%2,%3};\n"
        : "+f"(c[0]), "+f"(c[1]), "+f"(c[2]), "+f"(c[3])
        : "r"(a0), "r"(a1), "r"(a2), "r"(a3), "r"(b0), "r"(b1));
}
__device__ __forceinline__ void mma_tf32(float* c, const unsigned* a, unsigned b0, unsigned b1) {
    asm volatile(
        "mma.sync.aligned.m16n8k8.row.col.f32.tf32.tf32.f32 "
        "{%0,%1,%2,%3},{%4,%5,%6,%7},{%8,%9},{%0,%1,%2,%3};\n"
        : "+f"(c[0]), "+f"(c[1]), "+f"(c[2]), "+f"(c[3])
        : "r"(a[0]), "r"(a[1]), "r"(a[2]), "r"(a[3]), "r"(b0), "r"(b1));
}

// job 0..27 -> (mt32, np8) with np8 >= 4*mt32
__device__ __forceinline__ void decode_job(int job, int& mt, int& np) {
    if (job < 13)      { mt = 0; np = job; }
    else if (job < 22) { mt = 1; np = 4 + (job - 13); }
    else if (job < 27) { mt = 2; np = 8 + (job - 22); }
    else               { mt = 3; np = 12; }
}

// One GEMM1 tile job (m32 x n8 x 4 types). Stages direct + mirror logits (bf16x2).
__device__ __forceinline__ void gemm1_job(char* smem, int mt, int np,
                                          uint32_t hb_u, int lane, int g, int t4,
                                          unsigned stgD[2][2], unsigned stgM[2][2]) {
    const char*  adj_sm = smem + OFF_ADJ;
    const uint4* atp4   = (const uint4*)(smem + OFF_ATP);
    const int r0 = mt * 32, jc0 = np * 8;

    int ra0 = r0 + (lane & 15);      if (ra0 > 103) ra0 = 103;   // zero rows
    int ra1 = r0 + 16 + (lane & 15); if (ra1 > 103) ra1 = 103;
    uint32_t a0_addr = hb_u + (uint32_t)(ra0 * HB + ((lane >> 4) << 2)) * 4u;
    uint32_t a1_addr = hb_u + (uint32_t)(ra1 * HB + ((lane >> 4) << 2)) * 4u;
    int rb = jc0 + (lane & 7);       // <= 103
    uint32_t b_addr = hb_u + (uint32_t)(rb * HB + (((lane >> 3) & 1) << 2)) * 4u;
    const uint4* pt = atp4 + t4;

    float c[2][4][4];
    #pragma unroll
    for (int m = 0; m < 2; ++m)
        #pragma unroll
        for (int t = 0; t < 4; ++t)
            #pragma unroll
            for (int p = 0; p < 4; ++p) c[m][t][p] = 0.f;

    #pragma unroll 2
    for (int ks = 0; ks < 8; ++ks) {
        unsigned A00, A01, A02, A03, A10, A11, A12, A13, B0, B1;
        ldsm_x4(A00, A01, A02, A03, a0_addr + ks * 32u);
        ldsm_x4(A10, A11, A12, A13, a1_addr + ks * 32u);
        ldsm_x2(B0, B1, b_addr + ks * 32u);
        uint4 ap0 = pt[ks * 8];
        uint4 ap1 = pt[ks * 8 + 4];
        {   unsigned s0 = mulbf2(B0, ap0.x), s1 = mulbf2(B1, ap1.x);
            mma_bf16(c[0][0], A00, A01, A02, A03, s0, s1);
            mma_bf16(c[1][0], A10, A11, A12, A13, s0, s1); }
        {   unsigned s0 = mulbf2(B0, ap0.y), s1 = mulbf2(B1, ap1.y);
            mma_bf16(c[0][1], A00, A01, A02, A03, s0, s1);
            mma_bf16(c[1][1], A10, A11, A12, A13, s0, s1); }
        {   unsigned s0 = mulbf2(B0, ap0.z), s1 = mulbf2(B1, ap1.z);
            mma_bf16(c[0][2], A00, A01, A02, A03, s0, s1);
            mma_bf16(c[1][2], A10, A11, A12, A13, s0, s1); }
        {   unsigned s0 = mulbf2(B0, ap0.w), s1 = mulbf2(B1, ap1.w);
            mma_bf16(c[0][3], A00, A01, A02, A03, s0, s1);
            mma_bf16(c[1][3], A10, A11, A12, A13, s0, s1); }
    }

    // epilogue: select by adj (direct) and adj^T (mirror), leaky-relu, stage bf16x2
    #pragma unroll
    for (int m = 0; m < 2; ++m) {
        #pragma unroll
        for (int hf = 0; hf < 2; ++hf) {
            int row = r0 + 16 * m + g + 8 * hf;
            float vD[2], vM[2];
            #pragma unroll
            for (int e = 0; e < 2; ++e) {
                int col = jc0 + 2 * t4 + e;
                int p = 2 * hf + e;
                float xD = NEG_INF_, xM = NEG_INF_;
                if (row < L_ && col < L_) {
                    int t = adj_sm[row * ADJS + col];
                    float x = (t == 1) ? c[m][0][p] : (t == 2) ? c[m][1][p] :
                              (t == 3) ? c[m][2][p] : (t == 4) ? c[m][3][p] : 0.f;
                    x = (x > 0.f) ? x : 0.2f * x;
                    xD = t ? x : NEG_INF_;
                    int tm = adj_sm[col * ADJS + row];
                    float y = (tm == 1) ? c[m][0][p] : (tm == 2) ? c[m][1][p] :
                              (tm == 3) ? c[m][2][p] : (tm == 4) ? c[m][3][p] : 0.f;
                    y = (y > 0.f) ? y : 0.2f * y;
                    xM = tm ? y : NEG_INF_;
                }
                vD[e] = xD; vM[e] = xM;
            }
            stgD[m][hf] = pack_bf16x2(vD[0], vD[1]);
            stgM[m][hf] = pack_bf16x2(vM[0], vM[1]);
        }
    }
}

__device__ __forceinline__ void wb_job(float* al_sm, int mt, int np, int g, int t4,
                                       const unsigned stgD[2][2], const unsigned stgM[2][2]) {
    const int r0 = mt * 32, jc0 = np * 8;
    const int col0 = jc0 + 2 * t4;          // <= 102
    #pragma unroll
    for (int m = 0; m < 2; ++m) {
        #pragma unroll
        for (int hf = 0; hf < 2; ++hf) {
            int row = r0 + 16 * m + g + 8 * hf;
            if (row < 104) {                 // direct (always covered cell)
                unsigned pk = stgD[m][hf];
                *(float2*)(al_sm + row * AS + col0) =
                    make_float2(__uint_as_float(pk << 16),
                                __uint_as_float(pk & 0xffff0000u));
            }
            if (row < L_) {                  // mirror into uncovered cells only
                unsigned pk = stgM[m][hf];
                #pragma unroll
                for (int e = 0; e < 2; ++e) {
                    int col = col0 + e;
                    bool covered = ((row >> 3) >= 4 * (col >> 5));
                    if (col < L_ && !covered) {
                        float v = e ? __uint_as_float(pk & 0xffff0000u)
                                    : __uint_as_float(pk << 16);
                        al_sm[col * AS + row] = v;
                    }
                }
            }
        }
    }
}

__global__ __launch_bounds__(512, 2)
void combine_graph_kernel(const int* __restrict__ inputs,
                          const int* __restrict__ adj,
                          const float* __restrict__ emb,
                          const float* __restrict__ a0p,
                          const float* __restrict__ a1p,
                          const float* __restrict__ a2p,
                          const float* __restrict__ a3p,
                          float* __restrict__ out)
{
    extern __shared__ char smem[];
    float*    h_sm   = (float*)(smem + OFF_H);
    unsigned* hb_sm  = (unsigned*)(smem + OFF_HB);
    unsigned* atp_sm = (unsigned*)(smem + OFF_ATP);
    char*     adj_sm = smem + OFF_ADJ;
    float*    al_sm  = (float*)(smem + OFF_AL);
    const uint32_t hb_u = smem_u32(smem + OFF_HB);

    const int b    = blockIdx.x;
    const int tid  = threadIdx.x;
    const int w    = tid >> 5;
    const int lane = tid & 31;
    const int g    = lane >> 2;
    const int t4   = lane & 3;

    const int* inp  = inputs + b * L_;
    const int* adjb = adj + (size_t)b * (L_ * L_);

    // ---------------- phase 0: loads ----------------
    if (tid < 256) {   // atp[wd] = {pack(a0),pack(a1),pack(a2),pack(a3)} for word wd
        int wd = tid & 63, k = tid >> 6;
        const float* ap = (k == 0) ? a0p : (k == 1) ? a1p : (k == 2) ? a2p : a3p;
        ((unsigned*)((uint4*)atp_sm + wd))[k] = pack_bf16x2(ap[2 * wd], ap[2 * wd + 1]);
    }
    // embedding gather -> h f32 (tf32, swizzled) + hb bf16; rows 100..103 zero
    for (int e = tid; e < 104 * 32; e += 512) {
        int r = e >> 5, q = e & 31;
        float4 v = make_float4(0.f, 0.f, 0.f, 0.f);
        if (r < L_) {
            int id = inp[r];
            v = ((const float4*)(emb + (size_t)id * D_))[q];
            v.x = rna_tf32(v.x); v.y = rna_tf32(v.y);
            v.z = rna_tf32(v.z); v.w = rna_tf32(v.w);
        }
        *(float4*)(h_sm + HW(r, 4 * q)) = v;
        uint2 p2 = make_uint2(pack_bf16x2(v.x, v.y), pack_bf16x2(v.z, v.w));
        *(uint2*)(hb_sm + r * HB + 2 * q) = p2;
    }
    // adj -> int8
    for (int e = tid; e < 2500; e += 512) {
        int i = e / 25, c = e % 25;
        int4 v = ((const int4*)(adjb + i * 100))[c];
        unsigned p = (unsigned)(v.x & 0xff) | ((unsigned)(v.y & 0xff) << 8)
                   | ((unsigned)(v.z & 0xff) << 16) | ((unsigned)(v.w & 0xff) << 24);
        *(unsigned*)(adj_sm + i * ADJS + c * 4) = p;
    }
    __syncthreads();

    // ---------- GEMM1: 28 upper-triangle m32xn8 tiles, 2 rounds over 16 warps ----------
    unsigned stgD[2][2][2], stgM[2][2][2];
    #pragma unroll
    for (int k = 0; k < 2; ++k) {
        int job = w + 16 * k;
        if (job < 28) {
            int mt, np; decode_job(job, mt, np);
            gemm1_job(smem, mt, np, hb_u, lane, g, t4, stgD[k], stgM[k]);
        }
    }
    __syncthreads();   // hb/atp/adj dead; al overlay valid

    #pragma unroll
    for (int k = 0; k < 2; ++k) {
        int job = w + 16 * k;
        if (job < 28) {
            int mt, np; decode_job(job, mt, np);
            wb_job(al_sm, mt, np, g, t4, stgD[k], stgM[k]);
        }
    }
    __syncthreads();

    // ---------------- softmax over j (float4 rows) ----------------
    for (int i = w; i < L_; i += 16) {
        float4 x = make_float4(NEG_INF_, NEG_INF_, NEG_INF_, NEG_INF_);
        if (lane < 26) x = *(const float4*)(al_sm + i * AS + 4 * lane);
        float mx = fmaxf(fmaxf(x.x, x.y), fmaxf(x.z, x.w));
        #pragma unroll
        for (int o = 16; o > 0; o >>= 1) mx = fmaxf(mx, __shfl_xor_sync(0xffffffffu, mx, o));
        float4 ev = make_float4(0.f, 0.f, 0.f, 0.f);
        if (lane < 25) {   // cols 100..103 (lane 25) are masked out
            ev.x = __expf(x.x - mx); ev.y = __expf(x.y - mx);
            ev.z = __expf(x.z - mx); ev.w = __expf(x.w - mx);
        }
        float s = (ev.x + ev.y) + (ev.z + ev.w);
        #pragma unroll
        for (int o = 16; o > 0; o >>= 1) s += __shfl_xor_sync(0xffffffffu, s, o);
        float inv = 1.f / s;
        if (lane < 26) {
            float4 r4 = make_float4(rna_tf32(ev.x * inv), rna_tf32(ev.y * inv),
                                    rna_tf32(ev.z * inv), rna_tf32(ev.w * inv));
            *(float4*)(al_sm + i * AS + 4 * lane) = r4;   // lane 25 writes zeros
        }
    }
    // zero alpha rows 100..103 (GEMM2 K padding)
    for (int e = tid; e < 4 * AS; e += 512) al_sm[L_ * AS + e] = 0.f;
    __syncthreads();

    // ---------------- GEMM2: out = alpha @ h (tf32) ----------------
    {
        const int i32 = w & 3;
        const int ntq = w >> 2;
        const int r0b = i32 * 32;
        const int nh2 = (i32 == 3) ? 1 : 2;
        float c2[4][2][4];
        #pragma unroll
        for (int n = 0; n < 4; ++n)
            #pragma unroll
            for (int h = 0; h < 2; ++h)
                #pragma unroll
                for (int r = 0; r < 4; ++r) c2[n][h][r] = 0.f;

        #pragma unroll 4
        for (int kt = 0; kt < 13; ++kt) {
            int col = kt * 8 + t4;
            unsigned A2[2][4];
            #pragma unroll
            for (int h = 0; h < 2; ++h) {
                if (h < nh2) {
                    int r = r0b + h * 16 + g;
                    A2[h][0] = __float_as_uint(al_sm[r * AS + col]);
                    A2[h][1] = (i32 == 3) ? 0u : __float_as_uint(al_sm[(r + 8) * AS + col]);
                    A2[h][2] = __float_as_uint(al_sm[r * AS + col + 4]);
                    A2[h][3] = (i32 == 3) ? 0u : __float_as_uint(al_sm[(r + 8) * AS + col + 4]);
                }
            }
            #pragma unroll
            for (int n = 0; n < 4; ++n) {
                int d = (ntq * 4 + n) * 8 + g;
                unsigned B0 = __float_as_uint(h_sm[HW(col, d)]);
                unsigned B1 = __float_as_uint(h_sm[HW(col + 4, d)]);
                mma_tf32(c2[n][0], A2[0], B0, B1);
                if (nh2 == 2) mma_tf32(c2[n][1], A2[1], B0, B1);
            }
        }
        float* outb = out + (size_t)b * (L_ * D_);
        #pragma unroll
        for (int n = 0; n < 4; ++n) {
            #pragma unroll
            for (int h = 0; h < 2; ++h) {
                if (h < nh2) {
                    #pragma unroll
                    for (int p = 0; p < 2; ++p) {
                        int row = r0b + h * 16 + g + p * 8;
                        if (row < L_) {
                            int colo = (ntq * 4 + n) * 8 + t4 * 2;
                            float2 v2 = make_float2(c2[n][h][p * 2], c2[n][h][p * 2 + 1]);
                            *(float2*)(outb + row * D_ + colo) = v2;
                        }
                    }
                }
            }
        }
    }
}

extern "C" void kernel_launch(void* const* d_in, const int* in_sizes, int n_in,
                              void* d_out, int out_size) {
    // metadata order: inputs, adj, mask_item, item, emb_table, a0, a1, a2, a3
    const int*   inputs = (const int*)d_in[0];
    const int*   adj    = (const int*)d_in[1];
    const float* emb    = (const float*)d_in[4];
    const float* a0     = (const float*)d_in[5];
    const float* a1     = (const float*)d_in[6];
    const float* a2     = (const float*)d_in[7];
    const float* a3     = (const float*)d_in[8];
    float* out = (float*)d_out;

    cudaFuncSetAttribute(combine_graph_kernel,
                         cudaFuncAttributeMaxDynamicSharedMemorySize, SMEM_TOTAL);

    combine_graph_kernel<<<B_, 512, SMEM_TOTAL>>>(inputs, adj, emb, a0, a1, a2, a3, out);
}